// round 1
// baseline (speedup 1.0000x reference)
#include <cuda_runtime.h>

#define C 128
#define MAXN 100000
#define LN_EPS 1e-5f

// Scratch (allocation-free rule: __device__ globals)
__device__ float4 g_h4[MAXN * 32];     // h = relu(layernorm(x)), [N,128]
__device__ float4 g_agg4[MAXN * 32];   // sum of neighbor messages, [N,128]
__device__ float  g_cnt[MAXN];         // in-degree (float)
__device__ int    g_is64;              // edge_index dtype flag

// ---------------------------------------------------------------------------
// K0: detect whether edge_index is int64 or int32.
// Read first min(1024, 2E_bytes/8) values as int64: if ALL lie in [0, N),
// it's int64 (packed int32 pairs would produce huge values whenever the
// high word (a node id, ~uniform in [0,100000)) is nonzero).
// ---------------------------------------------------------------------------
__global__ void k_detect(const void* ei_, int N, int E) {
    const long long* p = (const long long*)ei_;
    int n = E < 1024 ? E : 1024;   // safe: n*8 bytes < buffer size for either dtype
    bool ok = true;
    for (int i = threadIdx.x; i < n; i += blockDim.x) {
        long long v = p[i];
        if (v < 0 || v >= (long long)N) ok = false;
    }
    ok = __syncthreads_and(ok);
    if (threadIdx.x == 0) g_is64 = ok ? 1 : 0;
}

// ---------------------------------------------------------------------------
// K1: LayerNorm + ReLU, one warp per row. 1 float4 per lane.
// ---------------------------------------------------------------------------
__global__ void k_ln(const float* __restrict__ x,
                     const float* __restrict__ gamma,
                     const float* __restrict__ beta, int N) {
    int w    = (blockIdx.x * blockDim.x + threadIdx.x) >> 5;
    int lane = threadIdx.x & 31;
    if (w >= N) return;

    float4 v = ((const float4*)x)[(size_t)w * 32 + lane];
    float s  = v.x + v.y + v.z + v.w;
    float sq = v.x * v.x + v.y * v.y + v.z * v.z + v.w * v.w;
#pragma unroll
    for (int o = 16; o; o >>= 1) {
        s  += __shfl_xor_sync(0xffffffffu, s, o);
        sq += __shfl_xor_sync(0xffffffffu, sq, o);
    }
    float mu  = s * (1.0f / C);
    float var = sq * (1.0f / C) - mu * mu;
    float rs  = rsqrtf(var + LN_EPS);

    float4 g = ((const float4*)gamma)[lane];
    float4 b = ((const float4*)beta)[lane];
    float4 h;
    h.x = fmaxf(0.0f, (v.x - mu) * rs * g.x + b.x);
    h.y = fmaxf(0.0f, (v.y - mu) * rs * g.y + b.y);
    h.z = fmaxf(0.0f, (v.z - mu) * rs * g.z + b.z);
    h.w = fmaxf(0.0f, (v.w - mu) * rs * g.w + b.w);
    g_h4[(size_t)w * 32 + lane] = h;
}

// ---------------------------------------------------------------------------
// K2: zero agg + cnt
// ---------------------------------------------------------------------------
__global__ void k_zero(int N) {
    int i   = blockIdx.x * blockDim.x + threadIdx.x;
    int tot = N * 32;
    if (i < tot) g_agg4[i] = make_float4(0.f, 0.f, 0.f, 0.f);
    if (i < N)   g_cnt[i] = 0.f;
}

// ---------------------------------------------------------------------------
// K3: edge scatter. One warp per edge: lane l moves float4 #l of h[src] into
// agg[dst] via red.global.add.v4.f32 (no-return vector reduction, sm_90+).
// lane 0 bumps the degree counter.
// ---------------------------------------------------------------------------
__global__ void k_scatter(const void* ei_, int N, int E) {
    int w = (blockIdx.x * blockDim.x + threadIdx.x) >> 5;
    if (w >= E) return;
    int lane = threadIdx.x & 31;

    int s, d;
    if (g_is64) {
        const long long* ei = (const long long*)ei_;
        s = (int)ei[w];
        d = (int)ei[(size_t)E + w];
    } else {
        const int* ei = (const int*)ei_;
        s = ei[w];
        d = ei[(size_t)E + w];
    }

    float4 v = g_h4[(size_t)s * 32 + lane];
    float* p = (float*)g_agg4 + (size_t)d * C + lane * 4;
    asm volatile("red.global.add.v4.f32 [%0], {%1,%2,%3,%4};"
                 :: "l"(p), "f"(v.x), "f"(v.y), "f"(v.z), "f"(v.w)
                 : "memory");
    if (lane == 0) {
        asm volatile("red.global.add.f32 [%0], %1;"
                     :: "l"(g_cnt + d), "f"(1.0f)
                     : "memory");
    }
}

// ---------------------------------------------------------------------------
// K4: fused epilogue GEMM:
//   out[i,:] = concat(mean_i, h_i)[1x256] @ Wc[256x128] + b_l + x_i
// where Wc[k][n] = W_l[n][k] (k<128) else W_r[n][k-128].
// Wc staged in 128 KB SMEM once per block. Each warp computes 4 rows;
// per k: 1 LDS.128 (weights) + 4 SHFL (row broadcasts) + 16 FFMA.
// ---------------------------------------------------------------------------
__global__ void __launch_bounds__(512, 1)
k_gemm(const float* __restrict__ x,
       const float* __restrict__ Wl,
       const float* __restrict__ bl,
       const float* __restrict__ Wr,
       float* __restrict__ out, int N) {
    extern __shared__ float sW[];   // [256][128]
    int tid = threadIdx.x;

    for (int i = tid; i < 256 * 128; i += blockDim.x) {
        int k = i >> 7;
        int n = i & 127;
        sW[i] = (k < 128) ? Wl[n * 128 + k] : Wr[n * 128 + (k - 128)];
    }
    __syncthreads();

    int lane    = tid & 31;
    int warp    = (blockIdx.x * blockDim.x + tid) >> 5;
    int nwarps  = (gridDim.x * blockDim.x) >> 5;
    int ngroups = (N + 3) >> 2;
    float4 bv   = ((const float4*)bl)[lane];
    const float* agg = (const float*)g_agg4;
    const float* h   = (const float*)g_h4;

    for (int g = warp; g < ngroups; g += nwarps) {
        int base = g * 4;
        int nr   = N - base; if (nr > 4) nr = 4;

        float inv[4][8];
#pragma unroll
        for (int rr = 0; rr < 4; ++rr) {
            if (rr < nr) {
                int row = base + rr;
                float cnt = g_cnt[row];
                float sc  = cnt > 0.f ? 1.0f / cnt : 0.0f;
#pragma unroll
                for (int j = 0; j < 4; ++j)
                    inv[rr][j] = agg[(size_t)row * C + j * 32 + lane] * sc;
#pragma unroll
                for (int j = 0; j < 4; ++j)
                    inv[rr][4 + j] = h[(size_t)row * C + j * 32 + lane];
            } else {
#pragma unroll
                for (int j = 0; j < 8; ++j) inv[rr][j] = 0.f;
            }
        }

        float4 acc0 = make_float4(0.f,0.f,0.f,0.f);
        float4 acc1 = make_float4(0.f,0.f,0.f,0.f);
        float4 acc2 = make_float4(0.f,0.f,0.f,0.f);
        float4 acc3 = make_float4(0.f,0.f,0.f,0.f);

        const float4* sW4 = (const float4*)sW;
#pragma unroll
        for (int j = 0; j < 8; ++j) {
            float a0 = inv[0][j], a1 = inv[1][j], a2 = inv[2][j], a3 = inv[3][j];
#pragma unroll 8
            for (int t = 0; t < 32; ++t) {
                int k = j * 32 + t;
                float4 wv = sW4[k * 32 + lane];
                float b0 = __shfl_sync(0xffffffffu, a0, t);
                float b1 = __shfl_sync(0xffffffffu, a1, t);
                float b2 = __shfl_sync(0xffffffffu, a2, t);
                float b3 = __shfl_sync(0xffffffffu, a3, t);
                acc0.x = fmaf(b0, wv.x, acc0.x); acc0.y = fmaf(b0, wv.y, acc0.y);
                acc0.z = fmaf(b0, wv.z, acc0.z); acc0.w = fmaf(b0, wv.w, acc0.w);
                acc1.x = fmaf(b1, wv.x, acc1.x); acc1.y = fmaf(b1, wv.y, acc1.y);
                acc1.z = fmaf(b1, wv.z, acc1.z); acc1.w = fmaf(b1, wv.w, acc1.w);
                acc2.x = fmaf(b2, wv.x, acc2.x); acc2.y = fmaf(b2, wv.y, acc2.y);
                acc2.z = fmaf(b2, wv.z, acc2.z); acc2.w = fmaf(b2, wv.w, acc2.w);
                acc3.x = fmaf(b3, wv.x, acc3.x); acc3.y = fmaf(b3, wv.y, acc3.y);
                acc3.z = fmaf(b3, wv.z, acc3.z); acc3.w = fmaf(b3, wv.w, acc3.w);
            }
        }

        float4 accs[4] = {acc0, acc1, acc2, acc3};
#pragma unroll
        for (int rr = 0; rr < 4; ++rr) {
            if (rr < nr) {
                int row = base + rr;
                float4 xv = ((const float4*)x)[(size_t)row * 32 + lane];
                float4 o;
                o.x = accs[rr].x + bv.x + xv.x;
                o.y = accs[rr].y + bv.y + xv.y;
                o.z = accs[rr].z + bv.z + xv.z;
                o.w = accs[rr].w + bv.w + xv.w;
                ((float4*)out)[(size_t)row * 32 + lane] = o;
            }
        }
    }
}

// ---------------------------------------------------------------------------
extern "C" void kernel_launch(void* const* d_in, const int* in_sizes, int n_in,
                              void* d_out, int out_size) {
    const float* x     = (const float*)d_in[0];
    const void*  ei    = d_in[1];
    const float* gamma = (const float*)d_in[2];
    const float* beta  = (const float*)d_in[3];
    const float* Wl    = (const float*)d_in[4];
    const float* bl    = (const float*)d_in[5];
    const float* Wr    = (const float*)d_in[6];
    float*       out   = (float*)d_out;

    int N = in_sizes[0] / C;       // 100000
    int E = in_sizes[1] / 2;       // 1600000 (element count, dtype-independent)

    k_detect<<<1, 256>>>(ei, N, E);
    k_ln<<<(N + 7) / 8, 256>>>(x, gamma, beta, N);
    k_zero<<<(N * 32 + 255) / 256, 256>>>(N);
    k_scatter<<<(E + 7) / 8, 256>>>(ei, N, E);

    cudaFuncSetAttribute(k_gemm, cudaFuncAttributeMaxDynamicSharedMemorySize,
                         256 * 128 * (int)sizeof(float));
    int sms = 148;
    cudaDeviceGetAttribute(&sms, cudaDevAttrMultiProcessorCount, 0);
    k_gemm<<<sms, 512, 256 * 128 * (int)sizeof(float)>>>(x, Wl, bl, Wr, out, N);
}

// round 2
// speedup vs baseline: 1.3700x; 1.3700x over previous
#include <cuda_runtime.h>

#define C 128
#define MAXN 100000
#define MAXE 1600000
#define LN_EPS 1e-5f

// Scratch (allocation-free rule: __device__ globals)
__device__ float4 g_h4[MAXN * 32];      // h = relu(layernorm(x)), [N,128]
__device__ float4 g_mean4[MAXN * 32];   // mean of neighbor messages, [N,128]
__device__ int    g_rowstart[MAXN + 1]; // CSR row offsets (by dst)
__device__ int    g_cursor[MAXN];       // counts -> exclusive offsets -> fill cursor
__device__ int    g_csr[MAXE];          // src ids grouped by dst
__device__ int    g_blocksums[256];
__device__ int    g_is64;               // edge_index dtype flag

// ---------------------------------------------------------------------------
// K0: detect whether edge_index is int64 or int32.
// ---------------------------------------------------------------------------
__global__ void k_detect(const void* ei_, int N, int E) {
    const long long* p = (const long long*)ei_;
    int n = E < 1024 ? E : 1024;
    bool ok = true;
    for (int i = threadIdx.x; i < n; i += blockDim.x) {
        long long v = p[i];
        if (v < 0 || v >= (long long)N) ok = false;
    }
    ok = __syncthreads_and(ok);
    if (threadIdx.x == 0) g_is64 = ok ? 1 : 0;
}

__device__ __forceinline__ int load_edge(const void* ei_, size_t idx) {
    if (g_is64) return (int)((const long long*)ei_)[idx];
    return ((const int*)ei_)[idx];
}

// ---------------------------------------------------------------------------
// K1: LayerNorm + ReLU, one warp per row.
// ---------------------------------------------------------------------------
__global__ void k_ln(const float* __restrict__ x,
                     const float* __restrict__ gamma,
                     const float* __restrict__ beta, int N) {
    int w    = (blockIdx.x * blockDim.x + threadIdx.x) >> 5;
    int lane = threadIdx.x & 31;
    if (w >= N) return;

    float4 v = ((const float4*)x)[(size_t)w * 32 + lane];
    float s  = v.x + v.y + v.z + v.w;
    float sq = v.x * v.x + v.y * v.y + v.z * v.z + v.w * v.w;
#pragma unroll
    for (int o = 16; o; o >>= 1) {
        s  += __shfl_xor_sync(0xffffffffu, s, o);
        sq += __shfl_xor_sync(0xffffffffu, sq, o);
    }
    float mu  = s * (1.0f / C);
    float var = sq * (1.0f / C) - mu * mu;
    float rs  = rsqrtf(var + LN_EPS);

    float4 g = ((const float4*)gamma)[lane];
    float4 b = ((const float4*)beta)[lane];
    float4 h;
    h.x = fmaxf(0.0f, (v.x - mu) * rs * g.x + b.x);
    h.y = fmaxf(0.0f, (v.y - mu) * rs * g.y + b.y);
    h.z = fmaxf(0.0f, (v.z - mu) * rs * g.z + b.z);
    h.w = fmaxf(0.0f, (v.w - mu) * rs * g.w + b.w);
    g_h4[(size_t)w * 32 + lane] = h;
}

// ---------------------------------------------------------------------------
// K2: zero degree counts + rowstart[0]
// ---------------------------------------------------------------------------
__global__ void k_zero_cnt(int N) {
    int i = blockIdx.x * blockDim.x + threadIdx.x;
    if (i < N) g_cursor[i] = 0;
    if (i == 0) g_rowstart[0] = 0;
}

// ---------------------------------------------------------------------------
// K3: degree histogram over dst
// ---------------------------------------------------------------------------
__global__ void k_hist(const void* ei_, int N, int E) {
    int e = blockIdx.x * blockDim.x + threadIdx.x;
    if (e >= E) return;
    int d = load_edge(ei_, (size_t)E + e);
    atomicAdd(&g_cursor[d], 1);
}

// ---------------------------------------------------------------------------
// K4a/b/c: 3-phase exclusive scan of counts (1024 elems per block)
// ---------------------------------------------------------------------------
__global__ void k_scan1(int N) {
    __shared__ int sh[8];
    int b = blockIdx.x, t = threadIdx.x;
    int base = b * 1024;
    int sum = 0;
    for (int i = t; i < 1024; i += 256) {
        int idx = base + i;
        if (idx < N) sum += g_cursor[idx];
    }
#pragma unroll
    for (int o = 16; o; o >>= 1) sum += __shfl_xor_sync(0xffffffffu, sum, o);
    if ((t & 31) == 0) sh[t >> 5] = sum;
    __syncthreads();
    if (t == 0) {
        int tot = 0;
#pragma unroll
        for (int i = 0; i < 8; ++i) tot += sh[i];
        g_blocksums[b] = tot;
    }
}

__global__ void k_scan2(int nb) {
    __shared__ int sh[256];
    int t = threadIdx.x;
    int v = (t < nb) ? g_blocksums[t] : 0;
    sh[t] = v;
    __syncthreads();
    for (int o = 1; o < 256; o <<= 1) {
        int x = (t >= o) ? sh[t - o] : 0;
        __syncthreads();
        sh[t] += x;
        __syncthreads();
    }
    if (t < nb) g_blocksums[t] = sh[t] - v;   // exclusive
}

__global__ void k_scan3(int N) {
    __shared__ int wsum[8];
    int b = blockIdx.x, t = threadIdx.x;
    int lane = t & 31, wid = t >> 5;
    int idx0 = b * 1024 + t * 4;

    int c[4];
#pragma unroll
    for (int k = 0; k < 4; ++k)
        c[k] = (idx0 + k < N) ? g_cursor[idx0 + k] : 0;
    int tsum = c[0] + c[1] + c[2] + c[3];

    // warp inclusive scan of tsum
    int v = tsum;
#pragma unroll
    for (int o = 1; o < 32; o <<= 1) {
        int x = __shfl_up_sync(0xffffffffu, v, o);
        if (lane >= o) v += x;
    }
    if (lane == 31) wsum[wid] = v;
    __syncthreads();
    if (t == 0) {
        int run = 0;
#pragma unroll
        for (int i = 0; i < 8; ++i) { int w = wsum[i]; wsum[i] = run; run += w; }
    }
    __syncthreads();

    int texcl = (v - tsum) + wsum[wid];
    int run = g_blocksums[b] + texcl;
#pragma unroll
    for (int k = 0; k < 4; ++k) {
        int idx = idx0 + k;
        if (idx < N) {
            g_rowstart[idx] = run;
            g_cursor[idx]   = run;
            run += c[k];
            if (idx == N - 1) g_rowstart[N] = run;  // = E
        }
    }
}

// ---------------------------------------------------------------------------
// K5: fill CSR src lists
// ---------------------------------------------------------------------------
__global__ void k_fill(const void* ei_, int N, int E) {
    int e = blockIdx.x * blockDim.x + threadIdx.x;
    if (e >= E) return;
    int s = load_edge(ei_, e);
    int d = load_edge(ei_, (size_t)E + e);
    int pos = atomicAdd(&g_cursor[d], 1);
    g_csr[pos] = s;
}

// ---------------------------------------------------------------------------
// K6: gather-sum aggregation. One warp per dst node; lane = 1 float4 of C.
// Neighbor ids staged across lanes (32 per chunk) then broadcast via shuffle
// so the 512B h-gathers are independent (high MLP).
// ---------------------------------------------------------------------------
__global__ void k_agg(int N) {
    int w    = (blockIdx.x * blockDim.x + threadIdx.x) >> 5;
    int lane = threadIdx.x & 31;
    if (w >= N) return;

    int start = g_rowstart[w];
    int end   = g_rowstart[w + 1];
    int deg   = end - start;

    float4 acc = make_float4(0.f, 0.f, 0.f, 0.f);
    for (int base = start; base < end; base += 32) {
        int m = end - base; if (m > 32) m = 32;
        int s = (lane < m) ? g_csr[base + lane] : 0;
#pragma unroll 8
        for (int j = 0; j < 32; ++j) {
            if (j >= m) break;
            int sj = __shfl_sync(0xffffffffu, s, j);
            float4 v = g_h4[(size_t)sj * 32 + lane];
            acc.x += v.x; acc.y += v.y; acc.z += v.z; acc.w += v.w;
        }
    }
    float inv = deg > 0 ? 1.0f / (float)deg : 0.0f;
    acc.x *= inv; acc.y *= inv; acc.z *= inv; acc.w *= inv;
    g_mean4[(size_t)w * 32 + lane] = acc;
}

// ---------------------------------------------------------------------------
// packed f32x2 helpers (FFMA2 — 2x FLOP per issue slot, PTX-only)
// ---------------------------------------------------------------------------
__device__ __forceinline__ unsigned long long pack2(float v) {
    unsigned long long r;
    asm("mov.b64 %0, {%1, %1};" : "=l"(r) : "f"(v));
    return r;
}
__device__ __forceinline__ void ffma2(unsigned long long& acc,
                                      unsigned long long a,
                                      unsigned long long b) {
    asm("fma.rn.f32x2 %0, %1, %2, %3;" : "=l"(acc) : "l"(a), "l"(b), "l"(acc));
}
__device__ __forceinline__ float2 unpack2(unsigned long long v) {
    float lo, hi;
    asm("mov.b64 {%0, %1}, %2;" : "=f"(lo), "=f"(hi) : "l"(v));
    return make_float2(lo, hi);
}

// ---------------------------------------------------------------------------
// K7: fused epilogue GEMM with FFMA2:
//   out[i,:] = concat(mean_i, h_i)[1x256] @ Wc[256x128] + b_l + x_i
// Wc (128KB) staged in SMEM; each warp computes 4 rows, lane covers 4 cols
// held as 2 packed f32x2 accumulators per row.
// ---------------------------------------------------------------------------
__global__ void __launch_bounds__(512, 1)
k_gemm(const float* __restrict__ x,
       const float* __restrict__ Wl,
       const float* __restrict__ bl,
       const float* __restrict__ Wr,
       float* __restrict__ out, int N) {
    extern __shared__ float sW[];   // [256][128]
    int tid = threadIdx.x;

    for (int i = tid; i < 256 * 128; i += blockDim.x) {
        int k = i >> 7;
        int n = i & 127;
        sW[i] = (k < 128) ? Wl[n * 128 + k] : Wr[n * 128 + (k - 128)];
    }
    __syncthreads();

    int lane    = tid & 31;
    int warp    = (blockIdx.x * blockDim.x + tid) >> 5;
    int nwarps  = (gridDim.x * blockDim.x) >> 5;
    int ngroups = (N + 3) >> 2;
    float4 bv   = ((const float4*)bl)[lane];
    const float* mean = (const float*)g_mean4;
    const float* h    = (const float*)g_h4;

    const ulonglong2* sW2 = (const ulonglong2*)sW;

    for (int g = warp; g < ngroups; g += nwarps) {
        int base = g * 4;
        int nr   = N - base; if (nr > 4) nr = 4;

        float inv[4][8];
#pragma unroll
        for (int rr = 0; rr < 4; ++rr) {
            if (rr < nr) {
                int row = base + rr;
#pragma unroll
                for (int j = 0; j < 4; ++j)
                    inv[rr][j] = mean[(size_t)row * C + j * 32 + lane];
#pragma unroll
                for (int j = 0; j < 4; ++j)
                    inv[rr][4 + j] = h[(size_t)row * C + j * 32 + lane];
            } else {
#pragma unroll
                for (int j = 0; j < 8; ++j) inv[rr][j] = 0.f;
            }
        }

        unsigned long long acc[4][2] = {};

#pragma unroll
        for (int j = 0; j < 8; ++j) {
            float a0 = inv[0][j], a1 = inv[1][j], a2 = inv[2][j], a3 = inv[3][j];
#pragma unroll 8
            for (int t = 0; t < 32; ++t) {
                int k = j * 32 + t;
                ulonglong2 wv = sW2[k * 32 + lane];
                unsigned long long p0 = pack2(__shfl_sync(0xffffffffu, a0, t));
                unsigned long long p1 = pack2(__shfl_sync(0xffffffffu, a1, t));
                unsigned long long p2 = pack2(__shfl_sync(0xffffffffu, a2, t));
                unsigned long long p3 = pack2(__shfl_sync(0xffffffffu, a3, t));
                ffma2(acc[0][0], p0, wv.x); ffma2(acc[0][1], p0, wv.y);
                ffma2(acc[1][0], p1, wv.x); ffma2(acc[1][1], p1, wv.y);
                ffma2(acc[2][0], p2, wv.x); ffma2(acc[2][1], p2, wv.y);
                ffma2(acc[3][0], p3, wv.x); ffma2(acc[3][1], p3, wv.y);
            }
        }

#pragma unroll
        for (int rr = 0; rr < 4; ++rr) {
            if (rr < nr) {
                int row = base + rr;
                float2 lo = unpack2(acc[rr][0]);
                float2 hi = unpack2(acc[rr][1]);
                float4 xv = ((const float4*)x)[(size_t)row * 32 + lane];
                float4 o;
                o.x = lo.x + bv.x + xv.x;
                o.y = lo.y + bv.y + xv.y;
                o.z = hi.x + bv.z + xv.z;
                o.w = hi.y + bv.w + xv.w;
                ((float4*)out)[(size_t)row * 32 + lane] = o;
            }
        }
    }
}

// ---------------------------------------------------------------------------
extern "C" void kernel_launch(void* const* d_in, const int* in_sizes, int n_in,
                              void* d_out, int out_size) {
    const float* x     = (const float*)d_in[0];
    const void*  ei    = d_in[1];
    const float* gamma = (const float*)d_in[2];
    const float* beta  = (const float*)d_in[3];
    const float* Wl    = (const float*)d_in[4];
    const float* bl    = (const float*)d_in[5];
    const float* Wr    = (const float*)d_in[6];
    float*       out   = (float*)d_out;

    int N = in_sizes[0] / C;       // 100000
    int E = in_sizes[1] / 2;       // 1600000

    int nb = (N + 1023) / 1024;    // scan blocks

    k_detect<<<1, 256>>>(ei, N, E);
    k_ln<<<(N + 7) / 8, 256>>>(x, gamma, beta, N);
    k_zero_cnt<<<(N + 255) / 256, 256>>>(N);
    k_hist<<<(E + 255) / 256, 256>>>(ei, N, E);
    k_scan1<<<nb, 256>>>(N);
    k_scan2<<<1, 256>>>(nb);
    k_scan3<<<nb, 256>>>(N);
    k_fill<<<(E + 255) / 256, 256>>>(ei, N, E);
    k_agg<<<(N + 7) / 8, 256>>>(N);

    cudaFuncSetAttribute(k_gemm, cudaFuncAttributeMaxDynamicSharedMemorySize,
                         256 * 128 * (int)sizeof(float));
    int sms = 148;
    cudaDeviceGetAttribute(&sms, cudaDevAttrMultiProcessorCount, 0);
    k_gemm<<<sms, 512, 256 * 128 * (int)sizeof(float)>>>(x, Wl, bl, Wr, out, N);
}

// round 4
// speedup vs baseline: 2.1141x; 1.5432x over previous
#include <cuda_runtime.h>
#include <cstdint>

#define C 128
#define MAXN 100000
#define MAXE 1600000
#define LN_EPS 1e-5f

// Scratch (allocation-free rule: __device__ globals)
__device__ float4 g_h4[MAXN * 32];      // h = relu(layernorm(x)), [N,128]
__device__ float4 g_mean4[MAXN * 32];   // mean of neighbor messages, [N,128]
__device__ int    g_rowstart[MAXN + 1]; // CSR row offsets (by dst)
__device__ int    g_cursor[MAXN];       // counts -> offsets -> fill cursor
__device__ int    g_csr[MAXE];          // src ids grouped by dst
__device__ int    g_blocksums[256];
__device__ int    g_is64;               // edge_index dtype flag

// ===========================================================================
// K0: edge_index dtype detection
// ===========================================================================
__global__ void k_detect(const void* ei_, int N, int E) {
    const long long* p = (const long long*)ei_;
    int n = E < 1024 ? E : 1024;
    bool ok = true;
    for (int i = threadIdx.x; i < n; i += blockDim.x) {
        long long v = p[i];
        if (v < 0 || v >= (long long)N) ok = false;
    }
    ok = __syncthreads_and(ok);
    if (threadIdx.x == 0) g_is64 = ok ? 1 : 0;
}

__device__ __forceinline__ int load_edge(const void* ei_, size_t idx) {
    if (g_is64) return (int)((const long long*)ei_)[idx];
    return ((const int*)ei_)[idx];
}

// ===========================================================================
// K1: LayerNorm + ReLU, one warp per row.
// ===========================================================================
__global__ void k_ln(const float* __restrict__ x,
                     const float* __restrict__ gamma,
                     const float* __restrict__ beta, int N) {
    int w    = (blockIdx.x * blockDim.x + threadIdx.x) >> 5;
    int lane = threadIdx.x & 31;
    if (w >= N) return;

    float4 v = ((const float4*)x)[(size_t)w * 32 + lane];
    float s  = v.x + v.y + v.z + v.w;
    float sq = v.x * v.x + v.y * v.y + v.z * v.z + v.w * v.w;
#pragma unroll
    for (int o = 16; o; o >>= 1) {
        s  += __shfl_xor_sync(0xffffffffu, s, o);
        sq += __shfl_xor_sync(0xffffffffu, sq, o);
    }
    float mu  = s * (1.0f / C);
    float var = sq * (1.0f / C) - mu * mu;
    float rs  = rsqrtf(var + LN_EPS);

    float4 g = ((const float4*)gamma)[lane];
    float4 b = ((const float4*)beta)[lane];
    float4 h;
    h.x = fmaxf(0.0f, (v.x - mu) * rs * g.x + b.x);
    h.y = fmaxf(0.0f, (v.y - mu) * rs * g.y + b.y);
    h.z = fmaxf(0.0f, (v.z - mu) * rs * g.z + b.z);
    h.w = fmaxf(0.0f, (v.w - mu) * rs * g.w + b.w);
    g_h4[(size_t)w * 32 + lane] = h;
}

// ===========================================================================
// K2: zero degree counts
// ===========================================================================
__global__ void k_zero_cnt(int N) {
    int i = blockIdx.x * blockDim.x + threadIdx.x;
    if (i < N) g_cursor[i] = 0;
    if (i == 0) g_rowstart[0] = 0;
}

// ===========================================================================
// K3: degree histogram over dst
// ===========================================================================
__global__ void k_hist(const void* ei_, int N, int E) {
    int e = blockIdx.x * blockDim.x + threadIdx.x;
    if (e >= E) return;
    int d = load_edge(ei_, (size_t)E + e);
    atomicAdd(&g_cursor[d], 1);
}

// ===========================================================================
// K4: 3-phase exclusive scan
// ===========================================================================
__global__ void k_scan1(int N) {
    __shared__ int sh[8];
    int b = blockIdx.x, t = threadIdx.x;
    int base = b * 1024;
    int sum = 0;
    for (int i = t; i < 1024; i += 256) {
        int idx = base + i;
        if (idx < N) sum += g_cursor[idx];
    }
#pragma unroll
    for (int o = 16; o; o >>= 1) sum += __shfl_xor_sync(0xffffffffu, sum, o);
    if ((t & 31) == 0) sh[t >> 5] = sum;
    __syncthreads();
    if (t == 0) {
        int tot = 0;
#pragma unroll
        for (int i = 0; i < 8; ++i) tot += sh[i];
        g_blocksums[b] = tot;
    }
}

__global__ void k_scan2(int nb) {
    __shared__ int sh[256];
    int t = threadIdx.x;
    int v = (t < nb) ? g_blocksums[t] : 0;
    sh[t] = v;
    __syncthreads();
    for (int o = 1; o < 256; o <<= 1) {
        int x = (t >= o) ? sh[t - o] : 0;
        __syncthreads();
        sh[t] += x;
        __syncthreads();
    }
    if (t < nb) g_blocksums[t] = sh[t] - v;
}

__global__ void k_scan3(int N) {
    __shared__ int wsum[8];
    int b = blockIdx.x, t = threadIdx.x;
    int lane = t & 31, wid = t >> 5;
    int idx0 = b * 1024 + t * 4;

    int c[4];
#pragma unroll
    for (int k = 0; k < 4; ++k)
        c[k] = (idx0 + k < N) ? g_cursor[idx0 + k] : 0;
    int tsum = c[0] + c[1] + c[2] + c[3];

    int v = tsum;
#pragma unroll
    for (int o = 1; o < 32; o <<= 1) {
        int xx = __shfl_up_sync(0xffffffffu, v, o);
        if (lane >= o) v += xx;
    }
    if (lane == 31) wsum[wid] = v;
    __syncthreads();
    if (t == 0) {
        int run = 0;
#pragma unroll
        for (int i = 0; i < 8; ++i) { int w = wsum[i]; wsum[i] = run; run += w; }
    }
    __syncthreads();

    int texcl = (v - tsum) + wsum[wid];
    int run = g_blocksums[b] + texcl;
#pragma unroll
    for (int k = 0; k < 4; ++k) {
        int idx = idx0 + k;
        if (idx < N) {
            g_rowstart[idx] = run;
            g_cursor[idx]   = run;
            run += c[k];
            if (idx == N - 1) g_rowstart[N] = run;
        }
    }
}

// ===========================================================================
// K5: fill CSR src lists
// ===========================================================================
__global__ void k_fill(const void* ei_, int N, int E) {
    int e = blockIdx.x * blockDim.x + threadIdx.x;
    if (e >= E) return;
    int s = load_edge(ei_, e);
    int d = load_edge(ei_, (size_t)E + e);
    int pos = atomicAdd(&g_cursor[d], 1);
    g_csr[pos] = s;
}

// ===========================================================================
// K6: gather-sum aggregation, one warp per dst node
// ===========================================================================
__global__ void k_agg(int N) {
    int w    = (blockIdx.x * blockDim.x + threadIdx.x) >> 5;
    int lane = threadIdx.x & 31;
    if (w >= N) return;

    int start = g_rowstart[w];
    int end   = g_rowstart[w + 1];
    int deg   = end - start;

    float4 acc = make_float4(0.f, 0.f, 0.f, 0.f);
    for (int base = start; base < end; base += 32) {
        int m = end - base; if (m > 32) m = 32;
        int s = (lane < m) ? g_csr[base + lane] : 0;
#pragma unroll 8
        for (int j = 0; j < 32; ++j) {
            if (j >= m) break;
            int sj = __shfl_sync(0xffffffffu, s, j);
            float4 v = g_h4[(size_t)sj * 32 + lane];
            acc.x += v.x; acc.y += v.y; acc.z += v.z; acc.w += v.w;
        }
    }
    float inv = deg > 0 ? 1.0f / (float)deg : 0.0f;
    acc.x *= inv; acc.y *= inv; acc.z *= inv; acc.w *= inv;
    g_mean4[(size_t)w * 32 + lane] = acc;
}

// ===========================================================================
// tf32 helpers (mma.sync path — plain sm_103-compatible PTX, sm_80+ baseline)
// ===========================================================================
__device__ __forceinline__ uint32_t to_tf32(float f) {
    uint32_t r;
    asm("cvt.rna.tf32.f32 %0, %1;" : "=r"(r) : "f"(f));
    return r;
}

__device__ __forceinline__ void mma_tf32(float4& d,
                                         uint32_t a0, uint32_t a1,
                                         uint32_t a2, uint32_t a3,
                                         uint32_t b0, uint32_t b1) {
    asm volatile(
        "mma.sync.aligned.m16n8k8.row.col.f32.tf32.tf32.f32 "
        "{%0,%1,%2,%3}, {%4,%5,%6,%7}, {%8,%9}, {%0,%1,%2,%3};"
        : "+f"(d.x), "+f"(d.y), "+f"(d.z), "+f"(d.w)
        : "r"(a0), "r"(a1), "r"(a2), "r"(a3), "r"(b0), "r"(b1));
}

// ===========================================================================
// K7: tensor-core GEMM epilogue via mma.sync m16n8k8 tf32.
//   out[128-row tile, 128] = mean @ Wl^T + h @ Wr^T + bias + x
// SMEM layout (floats):
//   sB: [128 n][260 pitch]  B[n][k] = Wl[n][k] (k<128) | Wr[n][k-128]
//   sA: [128 r][132 pitch]  current A half (mean, then h), tf32-rounded
//   sbias: [128]
// Frag-load bank pattern (4*ly+lx) is conflict-free for both arrays.
// ===========================================================================
#define BPITCH 260
#define APITCH 132
#define OFF_B  0
#define OFF_A  (128 * BPITCH)             // floats
#define OFF_BI (OFF_A + 128 * APITCH)     // floats
#define SMEM_FLOATS (OFF_BI + 128)
#define SMEM_TOT (SMEM_FLOATS * 4)

__global__ void __launch_bounds__(256, 1)
k_gemm_mma(const float* __restrict__ x,
           const float* __restrict__ Wl,
           const float* __restrict__ bl,
           const float* __restrict__ Wr,
           float* __restrict__ out, int N, int ntiles) {
    extern __shared__ float smem[];
    float* sB  = smem + OFF_B;
    float* sA  = smem + OFF_A;
    float* sbi = smem + OFF_BI;

    int tid  = threadIdx.x;
    int wid  = tid >> 5;
    int lane = tid & 31;
    int ly   = lane >> 2;   // groupID 0..7
    int lx   = lane & 3;    // threadID_in_group 0..3

    // Stage B (tf32-rounded), coalesced reads, contiguous SMEM writes.
    for (int i = tid; i < 128 * 128; i += 256) {
        int n = i >> 7, k = i & 127;
        sB[n * BPITCH + k]       = __uint_as_float(to_tf32(Wl[i]));
        sB[n * BPITCH + 128 + k] = __uint_as_float(to_tf32(Wr[i]));
    }
    for (int i = tid; i < 128; i += 256) sbi[i] = bl[i];
    __syncthreads();

    const float4* mean4 = g_mean4;
    const float4* h4    = g_h4;
    const uint32_t* sAu = (const uint32_t*)sA;
    const uint32_t* sBu = (const uint32_t*)sB;

    int rb = wid * 16;   // warp's row block within the tile

    for (int t = blockIdx.x; t < ntiles; t += gridDim.x) {
        int rbase = t * 128;
        float4 acc[16];
#pragma unroll
        for (int nt = 0; nt < 16; ++nt) acc[nt] = make_float4(0.f, 0.f, 0.f, 0.f);

#pragma unroll
        for (int half = 0; half < 2; ++half) {
            // stage A half (mean for half 0, h for half 1), tf32-rounded
            const float4* src = half ? h4 : mean4;
            for (int i = tid; i < 128 * 32; i += 256) {
                int r = i >> 5, kc = i & 31;
                int row = rbase + r;
                float4 v = (row < N) ? src[(size_t)row * 32 + kc]
                                     : make_float4(0.f, 0.f, 0.f, 0.f);
                float4 w;
                w.x = __uint_as_float(to_tf32(v.x));
                w.y = __uint_as_float(to_tf32(v.y));
                w.z = __uint_as_float(to_tf32(v.z));
                w.w = __uint_as_float(to_tf32(v.w));
                *(float4*)(sA + r * APITCH + kc * 4) = w;
            }
            __syncthreads();

            int kbase = half * 128;   // B column offset for this half
#pragma unroll
            for (int ks = 0; ks < 16; ++ks) {
                int kl = ks * 8;
                uint32_t a0 = sAu[(rb + ly)     * APITCH + kl + lx];
                uint32_t a1 = sAu[(rb + ly + 8) * APITCH + kl + lx];
                uint32_t a2 = sAu[(rb + ly)     * APITCH + kl + lx + 4];
                uint32_t a3 = sAu[(rb + ly + 8) * APITCH + kl + lx + 4];
#pragma unroll
                for (int nt = 0; nt < 16; ++nt) {
                    uint32_t b0 = sBu[(nt * 8 + ly) * BPITCH + kbase + kl + lx];
                    uint32_t b1 = sBu[(nt * 8 + ly) * BPITCH + kbase + kl + lx + 4];
                    mma_tf32(acc[nt], a0, a1, a2, a3, b0, b1);
                }
            }
            __syncthreads();   // acc lives in regs; sA can be restaged
        }

        // Epilogue: c0,c1 -> (row ly, cols 2lx,2lx+1); c2,c3 -> row ly+8
        int row0 = rbase + rb + ly;
        int row1 = row0 + 8;
#pragma unroll
        for (int nt = 0; nt < 16; ++nt) {
            int col = nt * 8 + lx * 2;
            float2 bv = *(const float2*)(sbi + col);
            if (row0 < N) {
                float2 xv = ((const float2*)x)[(size_t)row0 * 64 + (col >> 1)];
                float2 o = make_float2(acc[nt].x + bv.x + xv.x,
                                       acc[nt].y + bv.y + xv.y);
                ((float2*)out)[(size_t)row0 * 64 + (col >> 1)] = o;
            }
            if (row1 < N) {
                float2 xv = ((const float2*)x)[(size_t)row1 * 64 + (col >> 1)];
                float2 o = make_float2(acc[nt].z + bv.x + xv.x,
                                       acc[nt].w + bv.y + xv.y);
                ((float2*)out)[(size_t)row1 * 64 + (col >> 1)] = o;
            }
        }
        // no extra sync needed: next iteration's staging syncs before use
    }
}

// ===========================================================================
extern "C" void kernel_launch(void* const* d_in, const int* in_sizes, int n_in,
                              void* d_out, int out_size) {
    const float* x     = (const float*)d_in[0];
    const void*  ei    = d_in[1];
    const float* gamma = (const float*)d_in[2];
    const float* beta  = (const float*)d_in[3];
    const float* Wl    = (const float*)d_in[4];
    const float* bl    = (const float*)d_in[5];
    const float* Wr    = (const float*)d_in[6];
    float*       out   = (float*)d_out;

    int N = in_sizes[0] / C;       // 100000
    int E = in_sizes[1] / 2;       // 1600000
    int nb = (N + 1023) / 1024;
    int ntiles = (N + 127) / 128;

    k_detect<<<1, 256>>>(ei, N, E);
    k_ln<<<(N + 7) / 8, 256>>>(x, gamma, beta, N);
    k_zero_cnt<<<(N + 255) / 256, 256>>>(N);
    k_hist<<<(E + 255) / 256, 256>>>(ei, N, E);
    k_scan1<<<nb, 256>>>(N);
    k_scan2<<<1, 256>>>(nb);
    k_scan3<<<nb, 256>>>(N);
    k_fill<<<(E + 255) / 256, 256>>>(ei, N, E);
    k_agg<<<(N + 7) / 8, 256>>>(N);

    cudaFuncSetAttribute(k_gemm_mma, cudaFuncAttributeMaxDynamicSharedMemorySize,
                         SMEM_TOT);
    int sms = 148;
    cudaDeviceGetAttribute(&sms, cudaDevAttrMultiProcessorCount, 0);
    int grid = sms < ntiles ? sms : ntiles;
    k_gemm_mma<<<grid, 256, SMEM_TOT>>>(x, Wl, bl, Wr, out, N, ntiles);
}

// round 5
// speedup vs baseline: 2.4699x; 1.1683x over previous
#include <cuda_runtime.h>
#include <cuda_fp16.h>
#include <cstdint>

#define C 128
#define MAXN 100000
#define MAXE 1600000
#define LN_EPS 1e-5f

// Scratch (allocation-free rule: __device__ globals)
__device__ __half g_hh[MAXN * 128];     // h = relu(layernorm(x)), fp16 [N,128]
__device__ __half g_meanh[MAXN * 128];  // mean of neighbor messages, fp16 [N,128]
__device__ int    g_rowstart[MAXN + 1]; // CSR row offsets (by dst)
__device__ int    g_cursor[MAXN];       // counts -> offsets -> fill cursor
__device__ int    g_csr[MAXE];          // src ids grouped by dst
__device__ int    g_blocksums[256];
__device__ int    g_is64;               // edge_index dtype flag

// ===========================================================================
// K0: edge_index dtype detection
// ===========================================================================
__global__ void k_detect(const void* ei_, int N, int E) {
    const long long* p = (const long long*)ei_;
    int n = E < 1024 ? E : 1024;
    bool ok = true;
    for (int i = threadIdx.x; i < n; i += blockDim.x) {
        long long v = p[i];
        if (v < 0 || v >= (long long)N) ok = false;
    }
    ok = __syncthreads_and(ok);
    if (threadIdx.x == 0) g_is64 = ok ? 1 : 0;
}

__device__ __forceinline__ int load_edge(const void* ei_, size_t idx) {
    if (g_is64) return (int)((const long long*)ei_)[idx];
    return ((const int*)ei_)[idx];
}

// ===========================================================================
// K1: LayerNorm + ReLU, one warp per row; writes fp16 h.
// ===========================================================================
__global__ void k_ln(const float* __restrict__ x,
                     const float* __restrict__ gamma,
                     const float* __restrict__ beta, int N) {
    int w    = (blockIdx.x * blockDim.x + threadIdx.x) >> 5;
    int lane = threadIdx.x & 31;
    if (w >= N) return;

    float4 v = ((const float4*)x)[(size_t)w * 32 + lane];
    float s  = v.x + v.y + v.z + v.w;
    float sq = v.x * v.x + v.y * v.y + v.z * v.z + v.w * v.w;
#pragma unroll
    for (int o = 16; o; o >>= 1) {
        s  += __shfl_xor_sync(0xffffffffu, s, o);
        sq += __shfl_xor_sync(0xffffffffu, sq, o);
    }
    float mu  = s * (1.0f / C);
    float var = sq * (1.0f / C) - mu * mu;
    float rs  = rsqrtf(var + LN_EPS);

    float4 g = ((const float4*)gamma)[lane];
    float4 b = ((const float4*)beta)[lane];
    float hx = fmaxf(0.0f, (v.x - mu) * rs * g.x + b.x);
    float hy = fmaxf(0.0f, (v.y - mu) * rs * g.y + b.y);
    float hz = fmaxf(0.0f, (v.z - mu) * rs * g.z + b.z);
    float hw = fmaxf(0.0f, (v.w - mu) * rs * g.w + b.w);

    __half2 p0 = __floats2half2_rn(hx, hy);
    __half2 p1 = __floats2half2_rn(hz, hw);
    uint2 pk = make_uint2(*(uint32_t*)&p0, *(uint32_t*)&p1);
    ((uint2*)g_hh)[(size_t)w * 32 + lane] = pk;
}

// ===========================================================================
// K2: zero degree counts
// ===========================================================================
__global__ void k_zero_cnt(int N) {
    int i = blockIdx.x * blockDim.x + threadIdx.x;
    if (i < N) g_cursor[i] = 0;
    if (i == 0) g_rowstart[0] = 0;
}

// ===========================================================================
// K3: degree histogram over dst
// ===========================================================================
__global__ void k_hist(const void* ei_, int N, int E) {
    int e = blockIdx.x * blockDim.x + threadIdx.x;
    if (e >= E) return;
    int d = load_edge(ei_, (size_t)E + e);
    atomicAdd(&g_cursor[d], 1);
}

// ===========================================================================
// K4: 3-phase exclusive scan
// ===========================================================================
__global__ void k_scan1(int N) {
    __shared__ int sh[8];
    int b = blockIdx.x, t = threadIdx.x;
    int base = b * 1024;
    int sum = 0;
    for (int i = t; i < 1024; i += 256) {
        int idx = base + i;
        if (idx < N) sum += g_cursor[idx];
    }
#pragma unroll
    for (int o = 16; o; o >>= 1) sum += __shfl_xor_sync(0xffffffffu, sum, o);
    if ((t & 31) == 0) sh[t >> 5] = sum;
    __syncthreads();
    if (t == 0) {
        int tot = 0;
#pragma unroll
        for (int i = 0; i < 8; ++i) tot += sh[i];
        g_blocksums[b] = tot;
    }
}

__global__ void k_scan2(int nb) {
    __shared__ int sh[256];
    int t = threadIdx.x;
    int v = (t < nb) ? g_blocksums[t] : 0;
    sh[t] = v;
    __syncthreads();
    for (int o = 1; o < 256; o <<= 1) {
        int x = (t >= o) ? sh[t - o] : 0;
        __syncthreads();
        sh[t] += x;
        __syncthreads();
    }
    if (t < nb) g_blocksums[t] = sh[t] - v;
}

__global__ void k_scan3(int N) {
    __shared__ int wsum[8];
    int b = blockIdx.x, t = threadIdx.x;
    int lane = t & 31, wid = t >> 5;
    int idx0 = b * 1024 + t * 4;

    int c[4];
#pragma unroll
    for (int k = 0; k < 4; ++k)
        c[k] = (idx0 + k < N) ? g_cursor[idx0 + k] : 0;
    int tsum = c[0] + c[1] + c[2] + c[3];

    int v = tsum;
#pragma unroll
    for (int o = 1; o < 32; o <<= 1) {
        int xx = __shfl_up_sync(0xffffffffu, v, o);
        if (lane >= o) v += xx;
    }
    if (lane == 31) wsum[wid] = v;
    __syncthreads();
    if (t == 0) {
        int run = 0;
#pragma unroll
        for (int i = 0; i < 8; ++i) { int w = wsum[i]; wsum[i] = run; run += w; }
    }
    __syncthreads();

    int texcl = (v - tsum) + wsum[wid];
    int run = g_blocksums[b] + texcl;
#pragma unroll
    for (int k = 0; k < 4; ++k) {
        int idx = idx0 + k;
        if (idx < N) {
            g_rowstart[idx] = run;
            g_cursor[idx]   = run;
            run += c[k];
            if (idx == N - 1) g_rowstart[N] = run;
        }
    }
}

// ===========================================================================
// K5: fill CSR src lists
// ===========================================================================
__global__ void k_fill(const void* ei_, int N, int E) {
    int e = blockIdx.x * blockDim.x + threadIdx.x;
    if (e >= E) return;
    int s = load_edge(ei_, e);
    int d = load_edge(ei_, (size_t)E + e);
    int pos = atomicAdd(&g_cursor[d], 1);
    g_csr[pos] = s;
}

// ===========================================================================
// K6: gather-sum aggregation, one warp per dst node.
// fp16 messages: lane covers 4 halves (8B), fp32 accumulators.
// ===========================================================================
__global__ void k_agg(int N) {
    int w    = (blockIdx.x * blockDim.x + threadIdx.x) >> 5;
    int lane = threadIdx.x & 31;
    if (w >= N) return;

    int start = g_rowstart[w];
    int end   = g_rowstart[w + 1];
    int deg   = end - start;

    float4 acc = make_float4(0.f, 0.f, 0.f, 0.f);
    const uint2* hh = (const uint2*)g_hh;
    for (int base = start; base < end; base += 32) {
        int m = end - base; if (m > 32) m = 32;
        int s = (lane < m) ? g_csr[base + lane] : 0;
#pragma unroll 8
        for (int j = 0; j < 32; ++j) {
            if (j >= m) break;
            int sj = __shfl_sync(0xffffffffu, s, j);
            uint2 pk = hh[(size_t)sj * 32 + lane];
            float2 f0 = __half22float2(*(__half2*)&pk.x);
            float2 f1 = __half22float2(*(__half2*)&pk.y);
            acc.x += f0.x; acc.y += f0.y; acc.z += f1.x; acc.w += f1.y;
        }
    }
    float inv = deg > 0 ? 1.0f / (float)deg : 0.0f;
    __half2 p0 = __floats2half2_rn(acc.x * inv, acc.y * inv);
    __half2 p1 = __floats2half2_rn(acc.z * inv, acc.w * inv);
    ((uint2*)g_meanh)[(size_t)w * 32 + lane] =
        make_uint2(*(uint32_t*)&p0, *(uint32_t*)&p1);
}

// ===========================================================================
// tf32 helpers (mma.sync path — plain sm_103-compatible PTX)
// ===========================================================================
__device__ __forceinline__ uint32_t to_tf32(float f) {
    uint32_t r;
    asm("cvt.rna.tf32.f32 %0, %1;" : "=r"(r) : "f"(f));
    return r;
}

__device__ __forceinline__ void mma_tf32(float4& d,
                                         uint32_t a0, uint32_t a1,
                                         uint32_t a2, uint32_t a3,
                                         uint32_t b0, uint32_t b1) {
    asm volatile(
        "mma.sync.aligned.m16n8k8.row.col.f32.tf32.tf32.f32 "
        "{%0,%1,%2,%3}, {%4,%5,%6,%7}, {%8,%9}, {%0,%1,%2,%3};"
        : "+f"(d.x), "+f"(d.y), "+f"(d.z), "+f"(d.w)
        : "r"(a0), "r"(a1), "r"(a2), "r"(a3), "r"(b0), "r"(b1));
}

// ===========================================================================
// K7: tensor-core GEMM epilogue via mma.sync m16n8k8 tf32.
//   out[128-row tile, 128] = mean @ Wl^T + h @ Wr^T + bias + x
// A source is fp16 (exactly representable in tf32 -> no cvt needed for A).
// ===========================================================================
#define BPITCH 260
#define APITCH 132
#define OFF_B  0
#define OFF_A  (128 * BPITCH)             // floats
#define OFF_BI (OFF_A + 128 * APITCH)     // floats
#define SMEM_FLOATS (OFF_BI + 128)
#define SMEM_TOT (SMEM_FLOATS * 4)

__global__ void __launch_bounds__(256, 1)
k_gemm_mma(const float* __restrict__ x,
           const float* __restrict__ Wl,
           const float* __restrict__ bl,
           const float* __restrict__ Wr,
           float* __restrict__ out, int N, int ntiles) {
    extern __shared__ float smem[];
    float* sB  = smem + OFF_B;
    float* sA  = smem + OFF_A;
    float* sbi = smem + OFF_BI;

    int tid  = threadIdx.x;
    int wid  = tid >> 5;
    int lane = tid & 31;
    int ly   = lane >> 2;   // groupID 0..7
    int lx   = lane & 3;    // threadID_in_group 0..3

    // Stage B (tf32-rounded), coalesced reads, contiguous SMEM writes.
    for (int i = tid; i < 128 * 128; i += 256) {
        int n = i >> 7, k = i & 127;
        sB[n * BPITCH + k]       = __uint_as_float(to_tf32(Wl[i]));
        sB[n * BPITCH + 128 + k] = __uint_as_float(to_tf32(Wr[i]));
    }
    for (int i = tid; i < 128; i += 256) sbi[i] = bl[i];
    __syncthreads();

    const uint4* meanp = (const uint4*)g_meanh;  // 8 halves per uint4, 16/row
    const uint4* hp    = (const uint4*)g_hh;
    const uint32_t* sAu = (const uint32_t*)sA;
    const uint32_t* sBu = (const uint32_t*)sB;

    int rb = wid * 16;   // warp's row block within the tile

    for (int t = blockIdx.x; t < ntiles; t += gridDim.x) {
        int rbase = t * 128;
        float4 acc[16];
#pragma unroll
        for (int nt = 0; nt < 16; ++nt) acc[nt] = make_float4(0.f, 0.f, 0.f, 0.f);

#pragma unroll
        for (int half = 0; half < 2; ++half) {
            // stage A half (mean for half 0, h for half 1) from fp16
            const uint4* src = half ? hp : meanp;
            for (int i = tid; i < 128 * 16; i += 256) {
                int r = i >> 4, c8 = i & 15;     // c8: 8-half group
                int row = rbase + r;
                float4 w0, w1;
                if (row < N) {
                    uint4 pk = src[(size_t)row * 16 + c8];
                    float2 f0 = __half22float2(*(__half2*)&pk.x);
                    float2 f1 = __half22float2(*(__half2*)&pk.y);
                    float2 f2 = __half22float2(*(__half2*)&pk.z);
                    float2 f3 = __half22float2(*(__half2*)&pk.w);
                    w0 = make_float4(f0.x, f0.y, f1.x, f1.y);
                    w1 = make_float4(f2.x, f2.y, f3.x, f3.y);
                } else {
                    w0 = make_float4(0.f, 0.f, 0.f, 0.f);
                    w1 = w0;
                }
                *(float4*)(sA + r * APITCH + c8 * 8)     = w0;
                *(float4*)(sA + r * APITCH + c8 * 8 + 4) = w1;
            }
            __syncthreads();

            int kbase = half * 128;   // B column offset for this half
#pragma unroll
            for (int ks = 0; ks < 16; ++ks) {
                int kl = ks * 8;
                uint32_t a0 = sAu[(rb + ly)     * APITCH + kl + lx];
                uint32_t a1 = sAu[(rb + ly + 8) * APITCH + kl + lx];
                uint32_t a2 = sAu[(rb + ly)     * APITCH + kl + lx + 4];
                uint32_t a3 = sAu[(rb + ly + 8) * APITCH + kl + lx + 4];
#pragma unroll
                for (int nt = 0; nt < 16; ++nt) {
                    uint32_t b0 = sBu[(nt * 8 + ly) * BPITCH + kbase + kl + lx];
                    uint32_t b1 = sBu[(nt * 8 + ly) * BPITCH + kbase + kl + lx + 4];
                    mma_tf32(acc[nt], a0, a1, a2, a3, b0, b1);
                }
            }
            __syncthreads();   // acc lives in regs; sA can be restaged
        }

        // Epilogue: c0,c1 -> (row ly, cols 2lx,2lx+1); c2,c3 -> row ly+8
        int row0 = rbase + rb + ly;
        int row1 = row0 + 8;
#pragma unroll
        for (int nt = 0; nt < 16; ++nt) {
            int col = nt * 8 + lx * 2;
            float2 bv = *(const float2*)(sbi + col);
            if (row0 < N) {
                float2 xv = ((const float2*)x)[(size_t)row0 * 64 + (col >> 1)];
                float2 o = make_float2(acc[nt].x + bv.x + xv.x,
                                       acc[nt].y + bv.y + xv.y);
                ((float2*)out)[(size_t)row0 * 64 + (col >> 1)] = o;
            }
            if (row1 < N) {
                float2 xv = ((const float2*)x)[(size_t)row1 * 64 + (col >> 1)];
                float2 o = make_float2(acc[nt].z + bv.x + xv.x,
                                       acc[nt].w + bv.y + xv.y);
                ((float2*)out)[(size_t)row1 * 64 + (col >> 1)] = o;
            }
        }
    }
}

// ===========================================================================
extern "C" void kernel_launch(void* const* d_in, const int* in_sizes, int n_in,
                              void* d_out, int out_size) {
    const float* x     = (const float*)d_in[0];
    const void*  ei    = d_in[1];
    const float* gamma = (const float*)d_in[2];
    const float* beta  = (const float*)d_in[3];
    const float* Wl    = (const float*)d_in[4];
    const float* bl    = (const float*)d_in[5];
    const float* Wr    = (const float*)d_in[6];
    float*       out   = (float*)d_out;

    int N = in_sizes[0] / C;       // 100000
    int E = in_sizes[1] / 2;       // 1600000
    int nb = (N + 1023) / 1024;
    int ntiles = (N + 127) / 128;

    k_detect<<<1, 256>>>(ei, N, E);
    k_ln<<<(N + 7) / 8, 256>>>(x, gamma, beta, N);
    k_zero_cnt<<<(N + 255) / 256, 256>>>(N);
    k_hist<<<(E + 255) / 256, 256>>>(ei, N, E);
    k_scan1<<<nb, 256>>>(N);
    k_scan2<<<1, 256>>>(nb);
    k_scan3<<<nb, 256>>>(N);
    k_fill<<<(E + 255) / 256, 256>>>(ei, N, E);
    k_agg<<<(N + 7) / 8, 256>>>(N);

    cudaFuncSetAttribute(k_gemm_mma, cudaFuncAttributeMaxDynamicSharedMemorySize,
                         SMEM_TOT);
    int sms = 148;
    cudaDeviceGetAttribute(&sms, cudaDevAttrMultiProcessorCount, 0);
    int grid = sms < ntiles ? sms : ntiles;
    k_gemm_mma<<<grid, 256, SMEM_TOT>>>(x, Wl, bl, Wr, out, N, ntiles);
}